// round 2
// baseline (speedup 1.0000x reference)
#include <cuda_runtime.h>
#include <cuda_bf16.h>

#define F_IN   128
#define F_OUT  64
#define N_NODES_MAX 100000

#define TILE_M        128
#define GEMM_THREADS  128
#define XS_STRIDE     129   // pad to kill bank conflicts on Xs[row][k] reads

// smem: Xs[TILE_M][XS_STRIDE] + Ws[F_IN][F_OUT]
#define SMEM_FLOATS   (TILE_M * XS_STRIDE + F_IN * F_OUT)
#define SMEM_BYTES    (SMEM_FLOATS * 4)

// scratch for support = X @ W  (25.6 MB)
__device__ float g_support[(size_t)N_NODES_MAX * F_OUT];

// ---------------------------------------------------------------------------
// Kernel 1: support = X @ W
// 128x64 tile per 128-thread block; each thread computes 8 rows x 8 cols.
// ---------------------------------------------------------------------------
__global__ void gemm_support_kernel(const float* __restrict__ X,
                                    const float* __restrict__ W,
                                    int n_rows)
{
    extern __shared__ float smem[];
    float* Xs = smem;                          // [TILE_M][XS_STRIDE]
    float* Ws = smem + TILE_M * XS_STRIDE;     // [F_IN][F_OUT] row-major

    const int tid      = threadIdx.x;
    const int row_base = blockIdx.x * TILE_M;

    // ---- stage W (8192 floats = 2048 float4; 16 per thread) ----
    {
        const float4* W4  = (const float4*)W;
        float4*       Ws4 = (float4*)Ws;
        #pragma unroll
        for (int i = 0; i < (F_IN * F_OUT / 4) / GEMM_THREADS; i++)
            Ws4[tid + i * GEMM_THREADS] = W4[tid + i * GEMM_THREADS];
    }

    // ---- stage X tile: 128 rows x 128 cols = 4096 float4; 32 per thread ----
    #pragma unroll
    for (int i = 0; i < (TILE_M * F_IN / 4) / GEMM_THREADS; i++) {
        int idx = tid + i * GEMM_THREADS;   // 0..4095
        int r   = idx >> 5;                 // /(F_IN/4)
        int kq  = idx & 31;
        float4 v = make_float4(0.f, 0.f, 0.f, 0.f);
        int gr = row_base + r;
        if (gr < n_rows)
            v = ((const float4*)(X + (size_t)gr * F_IN))[kq];
        float* dstp = &Xs[r * XS_STRIDE + kq * 4];
        dstp[0] = v.x; dstp[1] = v.y; dstp[2] = v.z; dstp[3] = v.w;
    }
    __syncthreads();

    // ---- compute 8x8 micro-tile ----
    const int tx = tid & 7;     // col group: cols tx*8 .. tx*8+7
    const int ty = tid >> 3;    // row group: rows ty*8 .. ty*8+7
    const int c0 = tx * 8;
    const int r0 = ty * 8;

    float acc[8][8];
    #pragma unroll
    for (int i = 0; i < 8; i++)
        #pragma unroll
        for (int j = 0; j < 8; j++)
            acc[i][j] = 0.f;

    #pragma unroll 4
    for (int k = 0; k < F_IN; k++) {
        float xv[8];
        #pragma unroll
        for (int i = 0; i < 8; i++)
            xv[i] = Xs[(r0 + i) * XS_STRIDE + k];

        float4 w0 = *(const float4*)&Ws[k * F_OUT + c0];
        float4 w1 = *(const float4*)&Ws[k * F_OUT + c0 + 4];
        float wv[8] = { w0.x, w0.y, w0.z, w0.w, w1.x, w1.y, w1.z, w1.w };

        #pragma unroll
        for (int i = 0; i < 8; i++)
            #pragma unroll
            for (int j = 0; j < 8; j++)
                acc[i][j] += xv[i] * wv[j];
    }

    // ---- write support tile ----
    #pragma unroll
    for (int i = 0; i < 8; i++) {
        int gr = row_base + r0 + i;
        if (gr < n_rows) {
            float* o = g_support + (size_t)gr * F_OUT + c0;
            float4 a = make_float4(acc[i][0], acc[i][1], acc[i][2], acc[i][3]);
            float4 b = make_float4(acc[i][4], acc[i][5], acc[i][6], acc[i][7]);
            *(float4*)(o)     = a;
            *(float4*)(o + 4) = b;
        }
    }
}

// ---------------------------------------------------------------------------
// Kernel 2: out[i][c] = bias[c]
// ---------------------------------------------------------------------------
__global__ void init_out_kernel(float* __restrict__ out,
                                const float* __restrict__ bias,
                                int total)
{
    int i = blockIdx.x * blockDim.x + threadIdx.x;
    if (i < total)
        out[i] = __ldg(bias + (i & (F_OUT - 1)));
}

// ---------------------------------------------------------------------------
// Kernel 3: COO SPMM scatter-add. 16 threads per edge, float4 lanes,
// vectorized global reduction (red.global.add.v4.f32, no return trip).
// ---------------------------------------------------------------------------
__global__ void spmm_scatter_kernel(const float* __restrict__ ew,
                                    const int*  __restrict__ src,
                                    const int*  __restrict__ dst,
                                    float* __restrict__ out,
                                    int E)
{
    long long t = (long long)blockIdx.x * blockDim.x + threadIdx.x;
    int e = (int)(t >> 4);
    int q = (int)(t & 15);
    if (e >= E) return;

    int   s = __ldg(src + e);
    int   d = __ldg(dst + e);
    float w = __ldg(ew  + e);

    const float4 v = *(const float4*)(g_support + (size_t)s * F_OUT + q * 4);
    float* p = out + (size_t)d * F_OUT + q * 4;

    float m0 = v.x * w, m1 = v.y * w, m2 = v.z * w, m3 = v.w * w;
    asm volatile("red.global.add.v4.f32 [%0], {%1, %2, %3, %4};"
                 :: "l"(p), "f"(m0), "f"(m1), "f"(m2), "f"(m3)
                 : "memory");
}

// ---------------------------------------------------------------------------
extern "C" void kernel_launch(void* const* d_in, const int* in_sizes, int n_in,
                              void* d_out, int out_size)
{
    const float* x    = (const float*)d_in[0];   // [N, 128]
    const float* ew   = (const float*)d_in[1];   // [E]
    const float* W    = (const float*)d_in[2];   // [128, 64]
    const float* bias = (const float*)d_in[3];   // [64]
    const int*   src  = (const int*)  d_in[4];   // [E]
    const int*   dst  = (const int*)  d_in[5];   // [E]
    float*       out  = (float*)d_out;           // [N, 64]

    const int n = in_sizes[0] / F_IN;
    const int E = in_sizes[1];

    // raise dynamic smem limit for the GEMM kernel (idempotent, not a stream op)
    cudaFuncSetAttribute(gemm_support_kernel,
                         cudaFuncAttributeMaxDynamicSharedMemorySize, SMEM_BYTES);

    const int gemm_blocks = (n + TILE_M - 1) / TILE_M;
    gemm_support_kernel<<<gemm_blocks, GEMM_THREADS, SMEM_BYTES>>>(x, W, n);

    const int total = n * F_OUT;
    init_out_kernel<<<(total + 255) / 256, 256>>>(out, bias, total);

    const long long spmm_threads = (long long)E * 16;
    const int spmm_blocks = (int)((spmm_threads + 255) / 256);
    spmm_scatter_kernel<<<spmm_blocks, 256>>>(ew, src, dst, out, E);
}